// round 15
// baseline (speedup 1.0000x reference)
#include <cuda_runtime.h>
#include <cuda_bf16.h>
#include <cstdint>

// ---------------------------------------------------------------------------
// DeformableConvBlock: offset conv -> deformable sample+conv (HMMA bf16x3)
//                      -> BN -> +1x1 shortcut (HMMA, fused in gemm) -> relu
// B=8, CIN=128, COUT=256, H=W=64
// ---------------------------------------------------------------------------

#define B_    8
#define CIN_  128
#define COUT_ 256
#define H_    64
#define W_    64
#define HW_   4096
#define KTOT  1152           // CIN*9
#define EPS_  1e-5f
#define NPIX_ 32768          // B*H*W

// ---- device scratch (allocation-free rule) ----
__device__ float g_off[B_ * 18 * HW_];                     // offsets
__device__ float g_y[B_ * COUT_ * HW_];                    // pre-BN main out
__device__ float g_sc[B_ * COUT_ * HW_];                   // shortcut conv out
__device__ float g_scale[COUT_];
__device__ float g_shift[COUT_];
__device__ __align__(128) ushort g_wh[COUT_ * KTOT];       // w_def hi plane
__device__ __align__(128) ushort g_wl[COUT_ * KTOT];       // w_def lo plane
__device__ __align__(128) ushort g_sh[(size_t)NPIX_ * KTOT]; // im2col hi plane
__device__ __align__(128) ushort g_sl[(size_t)NPIX_ * KTOT]; // im2col lo plane
__device__ __align__(128) ushort g_wsh[COUT_ * CIN_];      // w_sc hi plane
__device__ __align__(128) ushort g_wsl[COUT_ * CIN_];      // w_sc lo plane
__device__ __align__(128) ushort g_xh[(size_t)NPIX_ * CIN_]; // x^T hi plane
__device__ __align__(128) ushort g_xl[(size_t)NPIX_ * CIN_]; // x^T lo plane

// ---- f32x2 helpers (scalar kernels) ----
__device__ __forceinline__ unsigned long long pack2(float a, float b) {
    unsigned long long r;
    asm("mov.b64 %0, {%1, %2};" : "=l"(r)
        : "r"(__float_as_uint(a)), "r"(__float_as_uint(b)));
    return r;
}
__device__ __forceinline__ float2 unpack2(unsigned long long v) {
    unsigned int a, b;
    asm("mov.b64 {%0, %1}, %2;" : "=r"(a), "=r"(b) : "l"(v));
    return make_float2(__uint_as_float(a), __uint_as_float(b));
}
__device__ __forceinline__ void fma2(unsigned long long& d,
                                     unsigned long long a, unsigned long long b) {
    asm("fma.rn.f32x2 %0, %1, %2, %0;" : "+l"(d) : "l"(a), "l"(b));
}

// ---- HMMA: m16n8k16 row.col f32.bf16.bf16.f32 ----
__device__ __forceinline__ void hmma(float* c, const unsigned* a, const unsigned* b) {
    asm("mma.sync.aligned.m16n8k16.row.col.f32.bf16.bf16.f32 "
        "{%0,%1,%2,%3}, {%4,%5,%6,%7}, {%8,%9}, {%0,%1,%2,%3};"
        : "+f"(c[0]), "+f"(c[1]), "+f"(c[2]), "+f"(c[3])
        : "r"(a[0]), "r"(a[1]), "r"(a[2]), "r"(a[3]), "r"(b[0]), "r"(b[1]));
}

#define LDSM4(d0, d1, d2, d3, addr)                                           \
    asm volatile("ldmatrix.sync.aligned.m8n8.x4.shared.b16 {%0,%1,%2,%3}, [%4];" \
        : "=r"(d0), "=r"(d1), "=r"(d2), "=r"(d3) : "r"(addr))

__device__ __forceinline__ uint32_t smem_u32(const void* p) {
    uint32_t a;
    asm("{ .reg .u64 t; cvta.to.shared.u64 t, %1; cvt.u32.u64 %0, t; }"
        : "=r"(a) : "l"(p));
    return a;
}

// ===========================================================================
// Kernel 1: offset conv  (3x3, pad 1, CIN=128 -> 18)
// ===========================================================================
__global__ __launch_bounds__(256, 1)
void k_offset(const float* __restrict__ x, const float* __restrict__ w_off,
              const float* __restrict__ b_off) {
    extern __shared__ float sm1[];
    float* ws = sm1;                 // 20736 floats
    float* xt = sm1 + 20736;         // [8][6][66]

    const int tid = threadIdx.x;
    const int b   = blockIdx.y;
    const int h0  = blockIdx.x * 4;

    for (int i = tid; i < 18 * CIN_ * 9; i += 256) {
        int co  = i / (CIN_ * 9);
        int r   = i - co * (CIN_ * 9);
        int cin = r / 9;
        int k   = r - cin * 9;
        ws[(cin * 9 + k) * 18 + co] = w_off[i];
    }

    const int rt = tid >> 6;
    const int wc = tid & 63;

    unsigned long long acc[9];
#pragma unroll
    for (int m = 0; m < 9; ++m) acc[m] = 0ull;

    const float* xb = x + ((size_t)b * CIN_) * HW_;
    __syncthreads();

    for (int it = 0; it < 16; ++it) {
        for (int i = tid; i < 8 * 396; i += 256) {
            int cc  = i / 396;
            int rem = i - cc * 396;
            int r   = rem / 66;
            int c2  = rem - r * 66;
            int gy  = h0 - 1 + r;
            int gx  = c2 - 1;
            float v = 0.f;
            if (gy >= 0 && gy < H_ && gx >= 0 && gx < W_)
                v = xb[(size_t)(it * 8 + cc) * HW_ + gy * W_ + gx];
            xt[i] = v;
        }
        __syncthreads();

#pragma unroll
        for (int cc = 0; cc < 8; ++cc) {
            const int cin = it * 8 + cc;
            float xv[9];
#pragma unroll
            for (int ky = 0; ky < 3; ++ky)
#pragma unroll
                for (int kx = 0; kx < 3; ++kx)
                    xv[ky * 3 + kx] = xt[cc * 396 + (rt + ky) * 66 + (wc + kx)];

#pragma unroll
            for (int k = 0; k < 9; ++k) {
                const unsigned long long* wp =
                    (const unsigned long long*)(ws) + (size_t)(cin * 9 + k) * 9;
                unsigned long long x2 = pack2(xv[k], xv[k]);
#pragma unroll
                for (int m = 0; m < 9; ++m) fma2(acc[m], wp[m], x2);
            }
        }
        __syncthreads();
    }

    float* ob = g_off + ((size_t)b * 18) * HW_ + (h0 + rt) * W_ + wc;
#pragma unroll
    for (int m = 0; m < 9; ++m) {
        float2 v = unpack2(acc[m]);
        ob[(2 * m) * HW_]     = v.x + b_off[2 * m];
        ob[(2 * m + 1) * HW_] = v.y + b_off[2 * m + 1];
    }
}

// ===========================================================================
// Kernel 2a/2b: split w_def / w_sc into bf16 hi / lo planes
// ===========================================================================
__global__ __launch_bounds__(1024)
void k_wsplit(const float* __restrict__ w) {
    int i = blockIdx.x * 1024 + threadIdx.x;
    float v = w[i];
    __nv_bfloat16 h = __float2bfloat16(v);
    float vh = __bfloat162float(h);
    __nv_bfloat16 l = __float2bfloat16(v - vh);
    g_wh[i] = __bfloat16_as_ushort(h);
    g_wl[i] = __bfloat16_as_ushort(l);
}
__global__ __launch_bounds__(1024)
void k_wscsplit(const float* __restrict__ w) {
    int i = blockIdx.x * 1024 + threadIdx.x;
    float v = w[i];
    __nv_bfloat16 h = __float2bfloat16(v);
    float vh = __bfloat162float(h);
    __nv_bfloat16 l = __float2bfloat16(v - vh);
    g_wsh[i] = __bfloat16_as_ushort(h);
    g_wsl[i] = __bfloat16_as_ushort(l);
}

// ===========================================================================
// Kernel 2c: transpose+split x -> g_xh/g_xl [pixel][cin]
// ===========================================================================
__global__ __launch_bounds__(256, 2)
void k_xsplit(const float* __restrict__ x) {
    __shared__ float xs[CIN_ * 65];
    const int tid = threadIdx.x;
    const int blk = blockIdx.x;
    const int b   = blk >> 6;
    const int h   = blk & 63;

    const float* xb = x + ((size_t)b * CIN_) * HW_ + h * 64;
#pragma unroll 8
    for (int i = 0; i < 32; ++i) {
        int e = tid + i * 256;
        int c = e >> 6, p = e & 63;
        xs[c * 65 + p] = xb[(size_t)c * HW_ + p];
    }
    __syncthreads();

    ushort* oh = g_xh + (size_t)(b * HW_ + h * 64) * CIN_;
    ushort* ol = g_xl + (size_t)(b * HW_ + h * 64) * CIN_;
#pragma unroll 8
    for (int i = 0; i < 32; ++i) {
        int e = tid + i * 256;
        int p = e >> 7, c = e & 127;
        float v = xs[c * 65 + p];
        __nv_bfloat16 hh = __float2bfloat16(v);
        float vh = __bfloat162float(hh);
        __nv_bfloat16 ll = __float2bfloat16(v - vh);
        oh[p * CIN_ + c] = __bfloat16_as_ushort(hh);
        ol[p * CIN_ + c] = __bfloat16_as_ushort(ll);
    }
}

// ===========================================================================
// Kernel 3: im2col — deformable bilinear gather -> bf16 hi/lo planes,
// S layout [pixel][1152]. Packed u32 stores (2 adjacent k per store).
// ===========================================================================
#define ICH  32
#define IKC  (ICH * 9)

__global__ __launch_bounds__(256, 2)
void k_im2col(const float* __restrict__ x) {
    extern __shared__ float smI[];
    float*  samp  = smI;                               // [288][65]
    int4*   tap_a = (int4*)(smI + IKC * 65);           // 576
    float4* tap_w = (float4*)(tap_a + 64 * 9);         // 576

    const int tid  = threadIdx.x;
    const int wid  = tid >> 5;
    const int lid  = tid & 31;
    const int blk  = blockIdx.x;
    const int bimg = blk >> 6;
    const int h    = blk & 63;

    for (int idx = tid; idx < 64 * 9; idx += 256) {
        int p = idx / 9;
        int k = idx - p * 9;
        const float* offb = g_off + ((size_t)bimg * 18) * HW_ + h * W_ + p;
        float dy = offb[(size_t)(2 * k) * HW_];
        float dx = offb[(size_t)(2 * k + 1) * HW_];
        float py = (float)(h + (k / 3) - 1) + dy;
        float px = (float)(p + (k % 3) - 1) + dx;
        float y0 = floorf(py), x0 = floorf(px);
        float fy = py - y0,    fx = px - x0;
        int iy = (int)y0, ix = (int)x0;
        float w00 = (1.f - fy) * (1.f - fx);
        float w01 = (1.f - fy) * fx;
        float w10 = fy * (1.f - fx);
        float w11 = fy * fx;
        int4 ad; float4 wt;
        bool vy0 = (iy >= 0)     && (iy < H_);
        bool vy1 = (iy + 1 >= 0) && (iy + 1 < H_);
        bool vx0 = (ix >= 0)     && (ix < W_);
        bool vx1 = (ix + 1 >= 0) && (ix + 1 < W_);
        ad.x = (vy0 && vx0) ? (iy * W_ + ix)           : 0;  wt.x = (vy0 && vx0) ? w00 : 0.f;
        ad.y = (vy0 && vx1) ? (iy * W_ + ix + 1)       : 0;  wt.y = (vy0 && vx1) ? w01 : 0.f;
        ad.z = (vy1 && vx0) ? ((iy + 1) * W_ + ix)     : 0;  wt.z = (vy1 && vx0) ? w10 : 0.f;
        ad.w = (vy1 && vx1) ? ((iy + 1) * W_ + ix + 1) : 0;  wt.w = (vy1 && vx1) ? w11 : 0.f;
        tap_a[idx] = ad;
        tap_w[idx] = wt;
    }
    __syncthreads();

    const float* xb = x + ((size_t)bimg * CIN_) * HW_;
    const size_t rowbase = (size_t)(bimg * HW_ + h * W_) * KTOT;

    for (int c0 = 0; c0 < CIN_; c0 += ICH) {
#pragma unroll 4
        for (int i = 0; i < IKC * 64 / 256; ++i) {
            int e  = i * 256 + tid;
            int p  = e & 63;
            int kk = e >> 6;
            int c  = kk / 9;
            int k  = kk - c * 9;
            int ti = p * 9 + k;
            int4   ad = tap_a[ti];
            float4 wt = tap_w[ti];
            const float* xc = xb + (size_t)(c0 + c) * HW_;
            samp[kk * 65 + p] = wt.x * __ldg(xc + ad.x) + wt.y * __ldg(xc + ad.y)
                              + wt.z * __ldg(xc + ad.z) + wt.w * __ldg(xc + ad.w);
        }
        __syncthreads();

        // transposed writeout: warp owns 8 pixels; lane packs 2 adjacent k
        for (int pi = 0; pi < 8; ++pi) {
            int p = wid * 8 + pi;
            size_t rb = rowbase + (size_t)p * KTOT + c0 * 9;   // even
            unsigned* rh32 = (unsigned*)(g_sh + rb);
            unsigned* rl32 = (unsigned*)(g_sl + rb);
#pragma unroll
            for (int pass = 0; pass < 5; ++pass) {
                int u = pass * 32 + lid;           // u32 index, 144 total
                if (u < 144) {
                    float v0 = samp[(2 * u)     * 65 + p];
                    float v1 = samp[(2 * u + 1) * 65 + p];
                    __nv_bfloat16 h0 = __float2bfloat16(v0);
                    __nv_bfloat16 h1 = __float2bfloat16(v1);
                    float r0 = v0 - __bfloat162float(h0);
                    float r1 = v1 - __bfloat162float(h1);
                    __nv_bfloat16 l0 = __float2bfloat16(r0);
                    __nv_bfloat16 l1 = __float2bfloat16(r1);
                    rh32[u] = (unsigned)__bfloat16_as_ushort(h0)
                            | ((unsigned)__bfloat16_as_ushort(h1) << 16);
                    rl32[u] = (unsigned)__bfloat16_as_ushort(l0)
                            | ((unsigned)__bfloat16_as_ushort(l1) << 16);
                }
            }
        }
        __syncthreads();
    }
}

// ===========================================================================
// Kernel 4: HMMA GEMM.  Block = M128 x N64 (grid (512, 2)), occ 2.
// 8 warps: 4M x 2N, warp tile 32x32. ldmatrix frags.
// Register-prefetch pipeline: LDG of chunk n+1 issued BEFORE compute of
// chunk n, so global latency hides under 96 HMMAs/warp of compute.
// smem rows: 64 ushorts = 128B = 8 x 16B sectors, sector ^= (row & 7).
// ===========================================================================
#define KC 64
#define OF_AH 0
#define OF_AL 16384
#define OF_BH 32768
#define OF_BL 40960
#define SMEMG 49152

__device__ __forceinline__ void ldg_AB(
    uint4 ra[8], uint4 rb[4], int tid,
    const ushort* __restrict__ Ah, const ushort* __restrict__ Al, int strideA,
    const ushort* __restrict__ Bh, const ushort* __restrict__ Bl, int strideB)
{
#pragma unroll
    for (int it = 0; it < 8; ++it) {
        int idx  = tid + it * 256;       // 0..2047 (2 planes x 128 rows x 8 sec)
        int plane = idx >> 10;
        int rem   = idx & 1023;
        int row   = rem >> 3;
        int s     = rem & 7;
        const ushort* base = plane ? Al : Ah;
        ra[it] = *(const uint4*)(base + (size_t)row * strideA + s * 8);
    }
#pragma unroll
    for (int it = 0; it < 4; ++it) {
        int idx  = tid + it * 256;       // 0..1023 (2 planes x 64 rows x 8 sec)
        int plane = idx >> 9;
        int rem   = idx & 511;
        int row   = rem >> 3;
        int s     = rem & 7;
        const ushort* base = plane ? Bl : Bh;
        rb[it] = *(const uint4*)(base + (size_t)row * strideB + s * 8);
    }
}

__device__ __forceinline__ void sts_AB(char* bb, int tid,
                                       const uint4 ra[8], const uint4 rb[4])
{
#pragma unroll
    for (int it = 0; it < 8; ++it) {
        int idx  = tid + it * 256;
        int plane = idx >> 10;
        int rem   = idx & 1023;
        int row   = rem >> 3;
        int s     = rem & 7;
        *(uint4*)(bb + (plane ? OF_AL : OF_AH) + row * 128
                  + ((s ^ (row & 7)) << 4)) = ra[it];
    }
#pragma unroll
    for (int it = 0; it < 4; ++it) {
        int idx  = tid + it * 256;
        int plane = idx >> 9;
        int rem   = idx & 511;
        int row   = rem >> 3;
        int s     = rem & 7;
        *(uint4*)(bb + (plane ? OF_BL : OF_BH) + row * 128
                  + ((s ^ (row & 7)) << 4)) = rb[it];
    }
}

struct FragCtx {
    uint32_t aoff[2]; int ar7[2]; int asec;
    uint32_t boff[2]; int br7[2]; int bsec;
};

__device__ __forceinline__ void gemm_chunk(float acc[2][4][4],
                                           uint32_t bb, const FragCtx& fc)
{
#pragma unroll
    for (int ks = 0; ks < 4; ++ks) {
        unsigned aH[2][4], aL[2][4], bH[4][2], bL[4][2];
#pragma unroll
        for (int mf = 0; mf < 2; ++mf) {
            uint32_t so = (uint32_t)((((ks * 2 + fc.asec) ^ fc.ar7[mf])) << 4);
            LDSM4(aH[mf][0], aH[mf][1], aH[mf][2], aH[mf][3],
                  bb + OF_AH + fc.aoff[mf] + so);
            LDSM4(aL[mf][0], aL[mf][1], aL[mf][2], aL[mf][3],
                  bb + OF_AL + fc.aoff[mf] + so);
        }
#pragma unroll
        for (int j = 0; j < 2; ++j) {
            uint32_t so = (uint32_t)((((ks * 2 + fc.bsec) ^ fc.br7[j])) << 4);
            LDSM4(bH[2 * j][0], bH[2 * j][1], bH[2 * j + 1][0], bH[2 * j + 1][1],
                  bb + OF_BH + fc.boff[j] + so);
            LDSM4(bL[2 * j][0], bL[2 * j][1], bL[2 * j + 1][0], bL[2 * j + 1][1],
                  bb + OF_BL + fc.boff[j] + so);
        }
#pragma unroll
        for (int mf = 0; mf < 2; ++mf)
#pragma unroll
            for (int nf = 0; nf < 4; ++nf) {
                hmma(acc[mf][nf], aH[mf], bH[nf]);
                hmma(acc[mf][nf], aH[mf], bL[nf]);
                hmma(acc[mf][nf], aL[mf], bH[nf]);
            }
    }
}

__device__ __forceinline__ void store_tile(
    float* __restrict__ gbase, const float acc[2][4][4],
    const float* __restrict__ bias_arr,
    int mtile, int wm, int wn, int lane, int bimg, int poff)
{
    const int rquad = lane >> 2;
    const int dcol  = (lane & 3) * 2;
#pragma unroll
    for (int mf = 0; mf < 2; ++mf)
#pragma unroll
        for (int hr = 0; hr < 2; ++hr) {
            int cout = mtile * 128 + wm * 32 + mf * 16 + hr * 8 + rquad;
            float bias = __ldg(bias_arr + cout);
            float* dst = gbase + ((size_t)(bimg * COUT_ + cout)) * HW_
                       + poff + wn * 32 + dcol;
#pragma unroll
            for (int nf = 0; nf < 4; ++nf) {
                float2 v;
                v.x = acc[mf][nf][hr * 2 + 0] + bias;
                v.y = acc[mf][nf][hr * 2 + 1] + bias;
                *(float2*)(dst + nf * 8) = v;
            }
        }
}

__global__ __launch_bounds__(256, 2)
void k_gemm(const float* __restrict__ b_def, const float* __restrict__ b_sc) {
    extern __shared__ char smG[];
    const uint32_t smb = smem_u32(smG);

    const int tid  = threadIdx.x;
    const int lane = tid & 31;
    const int wid  = tid >> 5;
    const int wm   = wid & 3;           // 4 M-warps x 32 rows
    const int wn   = wid >> 2;          // 2 N-warps x 32 cols

    const int pix0  = blockIdx.x * 64;
    const int mtile = blockIdx.y;
    const int bimg  = pix0 >> 12;
    const int poff  = pix0 & 4095;

    FragCtx fc;
#pragma unroll
    for (int mf = 0; mf < 2; ++mf) {
        int row = wm * 32 + mf * 16 + ((lane >> 3) & 1) * 8 + (lane & 7);
        fc.aoff[mf] = row * 128;
        fc.ar7[mf]  = row & 7;
    }
    fc.asec = lane >> 4;
#pragma unroll
    for (int j = 0; j < 2; ++j) {
        int row = wn * 32 + j * 16 + ((lane >> 4) & 1) * 8 + (lane & 7);
        fc.boff[j] = row * 128;
        fc.br7[j]  = row & 7;
    }
    fc.bsec = (lane >> 3) & 1;

    float acc[2][4][4];
#pragma unroll
    for (int mf = 0; mf < 2; ++mf)
#pragma unroll
        for (int nf = 0; nf < 4; ++nf)
#pragma unroll
            for (int q = 0; q < 4; ++q) acc[mf][nf][q] = 0.f;

    uint4 ra[8], rb[4];

    // ---- main GEMM: K = 1152, register-prefetch pipeline ----
    const ushort* Ah = g_wh + (size_t)(mtile * 128) * KTOT;
    const ushort* Al = g_wl + (size_t)(mtile * 128) * KTOT;
    const ushort* Bh = g_sh + (size_t)pix0 * KTOT;
    const ushort* Bl = g_sl + (size_t)pix0 * KTOT;

    ldg_AB(ra, rb, tid, Ah, Al, KTOT, Bh, Bl, KTOT);

    const int NCH = KTOT / KC;          // 18
    for (int ch = 0; ch < NCH; ++ch) {
        __syncthreads();                // prev compute done -> buffer reusable
        sts_AB(smG, tid, ra, rb);
        __syncthreads();
        if (ch + 1 < NCH) {
            const int k1 = (ch + 1) * KC;
            ldg_AB(ra, rb, tid, Ah + k1, Al + k1, KTOT, Bh + k1, Bl + k1, KTOT);
        }
        gemm_chunk(acc, smb, fc);
    }
    store_tile(g_y, acc, b_def, mtile, wm, wn, lane, bimg, poff);

    // ---- shortcut GEMM: K = 128 (2 chunks), same pipeline ----
#pragma unroll
    for (int mf = 0; mf < 2; ++mf)
#pragma unroll
        for (int nf = 0; nf < 4; ++nf)
#pragma unroll
            for (int q = 0; q < 4; ++q) acc[mf][nf][q] = 0.f;

    const ushort* Ash = g_wsh + (size_t)(mtile * 128) * CIN_;
    const ushort* Asl = g_wsl + (size_t)(mtile * 128) * CIN_;
    const ushort* Bsh = g_xh + (size_t)pix0 * CIN_;
    const ushort* Bsl = g_xl + (size_t)pix0 * CIN_;

    ldg_AB(ra, rb, tid, Ash, Asl, CIN_, Bsh, Bsl, CIN_);
    for (int ch = 0; ch < 2; ++ch) {
        __syncthreads();
        sts_AB(smG, tid, ra, rb);
        __syncthreads();
        if (ch == 0)
            ldg_AB(ra, rb, tid, Ash + KC, Asl + KC, CIN_,
                   Bsh + KC, Bsl + KC, CIN_);
        gemm_chunk(acc, smb, fc);
    }
    store_tile(g_sc, acc, b_sc, mtile, wm, wn, lane, bimg, poff);
}

// ===========================================================================
// Kernel 5: BN batch stats
// ===========================================================================
__global__ __launch_bounds__(256)
void k_stats(const float* __restrict__ gamma, const float* __restrict__ beta) {
    const int co = blockIdx.x;
    const int t  = threadIdx.x;
    float s = 0.f, s2 = 0.f;
    for (int b = 0; b < B_; ++b) {
        const float* yb = g_y + ((size_t)(b * COUT_ + co)) * HW_;
        for (int i = t * 4; i < HW_; i += 1024) {
            float4 v = *(const float4*)(yb + i);
            s  += v.x + v.y + v.z + v.w;
            s2 += v.x * v.x + v.y * v.y + v.z * v.z + v.w * v.w;
        }
    }
    __shared__ float rs[256], rq[256];
    rs[t] = s; rq[t] = s2;
    __syncthreads();
    for (int off = 128; off; off >>= 1) {
        if (t < off) { rs[t] += rs[t + off]; rq[t] += rq[t + off]; }
        __syncthreads();
    }
    if (t == 0) {
        const float inv_n = 1.f / (float)(B_ * HW_);
        float mean = rs[0] * inv_n;
        float var  = rq[0] * inv_n - mean * mean;
        float istd = rsqrtf(var + EPS_);
        float g = gamma[co];
        g_scale[co] = g * istd;
        g_shift[co] = beta[co] - mean * g * istd;
    }
}

// ===========================================================================
// Kernel 6: elementwise  out = relu(y*scale + shift + sc)
// ===========================================================================
__global__ __launch_bounds__(256)
void k_final(float* __restrict__ out) {
    const size_t idx = ((size_t)blockIdx.x * 256 + threadIdx.x) * 4;
    const int c = (int)((idx >> 12) & 255);
    const float sc = g_scale[c];
    const float sh = g_shift[c];
    float4 y = *(const float4*)(g_y + idx);
    float4 s = *(const float4*)(g_sc + idx);
    float4 r;
    r.x = fmaxf(fmaf(y.x, sc, sh) + s.x, 0.f);
    r.y = fmaxf(fmaf(y.y, sc, sh) + s.y, 0.f);
    r.z = fmaxf(fmaf(y.z, sc, sh) + s.z, 0.f);
    r.w = fmaxf(fmaf(y.w, sc, sh) + s.w, 0.f);
    *(float4*)(out + idx) = r;
}

// ===========================================================================
extern "C" void kernel_launch(void* const* d_in, const int* in_sizes, int n_in,
                              void* d_out, int out_size) {
    const float* x     = (const float*)d_in[0];
    const float* w_off = (const float*)d_in[1];
    const float* b_off = (const float*)d_in[2];
    const float* w_def = (const float*)d_in[3];
    const float* b_def = (const float*)d_in[4];
    const float* gamma = (const float*)d_in[5];
    const float* beta  = (const float*)d_in[6];
    const float* w_sc  = (const float*)d_in[7];
    const float* b_sc  = (const float*)d_in[8];
    float* out = (float*)d_out;

    const int smem1 = (20736 + 8 * 396) * 4;
    const int smemI = (IKC * 65) * 4 + 64 * 9 * (sizeof(int4) + sizeof(float4));

    cudaFuncSetAttribute(k_offset, cudaFuncAttributeMaxDynamicSharedMemorySize, smem1);
    cudaFuncSetAttribute(k_im2col, cudaFuncAttributeMaxDynamicSharedMemorySize, smemI);
    cudaFuncSetAttribute(k_gemm,   cudaFuncAttributeMaxDynamicSharedMemorySize, SMEMG);

    k_offset<<<dim3(16, 8), 256, smem1>>>(x, w_off, b_off);
    k_wsplit<<<288, 1024>>>(w_def);
    k_wscsplit<<<32, 1024>>>(w_sc);
    k_xsplit<<<512, 256>>>(x);
    k_im2col<<<512, 256, smemI>>>(x);
    k_gemm<<<dim3(512, 2), 256, SMEMG>>>(b_def, b_sc);
    k_stats<<<256, 256>>>(gamma, beta);
    k_final<<<8192, 256>>>(out);
}

// round 17
// speedup vs baseline: 1.0473x; 1.0473x over previous
#include <cuda_runtime.h>
#include <cuda_bf16.h>
#include <cstdint>

// ---------------------------------------------------------------------------
// DeformableConvBlock: offset conv -> deformable sample+conv (HMMA bf16x3)
//                      -> BN -> +1x1 shortcut (HMMA, fused in gemm) -> relu
// B=8, CIN=128, COUT=256, H=W=64
// ---------------------------------------------------------------------------

#define B_    8
#define CIN_  128
#define COUT_ 256
#define H_    64
#define W_    64
#define HW_   4096
#define KTOT  1152           // CIN*9
#define EPS_  1e-5f
#define NPIX_ 32768          // B*H*W

// ---- device scratch (allocation-free rule) ----
__device__ float g_off[B_ * 18 * HW_];                     // offsets
__device__ float g_y[B_ * COUT_ * HW_];                    // pre-BN main out
__device__ float g_sc[B_ * COUT_ * HW_];                   // shortcut conv out
__device__ float g_scale[COUT_];
__device__ float g_shift[COUT_];
__device__ __align__(128) ushort g_wh[COUT_ * KTOT];       // w_def hi plane
__device__ __align__(128) ushort g_wl[COUT_ * KTOT];       // w_def lo plane
__device__ __align__(128) ushort g_sh[(size_t)NPIX_ * KTOT]; // im2col hi plane
__device__ __align__(128) ushort g_sl[(size_t)NPIX_ * KTOT]; // im2col lo plane
__device__ __align__(128) ushort g_wsh[COUT_ * CIN_];      // w_sc hi plane
__device__ __align__(128) ushort g_wsl[COUT_ * CIN_];      // w_sc lo plane
__device__ __align__(128) ushort g_xh[(size_t)NPIX_ * CIN_]; // x^T hi plane
__device__ __align__(128) ushort g_xl[(size_t)NPIX_ * CIN_]; // x^T lo plane

// ---- f32x2 helpers (scalar kernels) ----
__device__ __forceinline__ unsigned long long pack2(float a, float b) {
    unsigned long long r;
    asm("mov.b64 %0, {%1, %2};" : "=l"(r)
        : "r"(__float_as_uint(a)), "r"(__float_as_uint(b)));
    return r;
}
__device__ __forceinline__ float2 unpack2(unsigned long long v) {
    unsigned int a, b;
    asm("mov.b64 {%0, %1}, %2;" : "=r"(a), "=r"(b) : "l"(v));
    return make_float2(__uint_as_float(a), __uint_as_float(b));
}
__device__ __forceinline__ void fma2(unsigned long long& d,
                                     unsigned long long a, unsigned long long b) {
    asm("fma.rn.f32x2 %0, %1, %2, %0;" : "+l"(d) : "l"(a), "l"(b));
}

// ---- HMMA: m16n8k16 row.col f32.bf16.bf16.f32 ----
__device__ __forceinline__ void hmma(float* c, const unsigned* a, const unsigned* b) {
    asm("mma.sync.aligned.m16n8k16.row.col.f32.bf16.bf16.f32 "
        "{%0,%1,%2,%3}, {%4,%5,%6,%7}, {%8,%9}, {%0,%1,%2,%3};"
        : "+f"(c[0]), "+f"(c[1]), "+f"(c[2]), "+f"(c[3])
        : "r"(a[0]), "r"(a[1]), "r"(a[2]), "r"(a[3]), "r"(b[0]), "r"(b[1]));
}

#define LDSM4(d0, d1, d2, d3, addr)                                           \
    asm volatile("ldmatrix.sync.aligned.m8n8.x4.shared.b16 {%0,%1,%2,%3}, [%4];" \
        : "=r"(d0), "=r"(d1), "=r"(d2), "=r"(d3) : "r"(addr))

__device__ __forceinline__ uint32_t smem_u32(const void* p) {
    uint32_t a;
    asm("{ .reg .u64 t; cvta.to.shared.u64 t, %1; cvt.u32.u64 %0, t; }"
        : "=r"(a) : "l"(p));
    return a;
}

// ===========================================================================
// Kernel 1: offset conv  (3x3, pad 1, CIN=128 -> 18)
// ===========================================================================
__global__ __launch_bounds__(256, 1)
void k_offset(const float* __restrict__ x, const float* __restrict__ w_off,
              const float* __restrict__ b_off) {
    extern __shared__ float sm1[];
    float* ws = sm1;                 // 20736 floats
    float* xt = sm1 + 20736;         // [8][6][66]

    const int tid = threadIdx.x;
    const int b   = blockIdx.y;
    const int h0  = blockIdx.x * 4;

    for (int i = tid; i < 18 * CIN_ * 9; i += 256) {
        int co  = i / (CIN_ * 9);
        int r   = i - co * (CIN_ * 9);
        int cin = r / 9;
        int k   = r - cin * 9;
        ws[(cin * 9 + k) * 18 + co] = w_off[i];
    }

    const int rt = tid >> 6;
    const int wc = tid & 63;

    unsigned long long acc[9];
#pragma unroll
    for (int m = 0; m < 9; ++m) acc[m] = 0ull;

    const float* xb = x + ((size_t)b * CIN_) * HW_;
    __syncthreads();

    for (int it = 0; it < 16; ++it) {
        for (int i = tid; i < 8 * 396; i += 256) {
            int cc  = i / 396;
            int rem = i - cc * 396;
            int r   = rem / 66;
            int c2  = rem - r * 66;
            int gy  = h0 - 1 + r;
            int gx  = c2 - 1;
            float v = 0.f;
            if (gy >= 0 && gy < H_ && gx >= 0 && gx < W_)
                v = xb[(size_t)(it * 8 + cc) * HW_ + gy * W_ + gx];
            xt[i] = v;
        }
        __syncthreads();

#pragma unroll
        for (int cc = 0; cc < 8; ++cc) {
            const int cin = it * 8 + cc;
            float xv[9];
#pragma unroll
            for (int ky = 0; ky < 3; ++ky)
#pragma unroll
                for (int kx = 0; kx < 3; ++kx)
                    xv[ky * 3 + kx] = xt[cc * 396 + (rt + ky) * 66 + (wc + kx)];

#pragma unroll
            for (int k = 0; k < 9; ++k) {
                const unsigned long long* wp =
                    (const unsigned long long*)(ws) + (size_t)(cin * 9 + k) * 9;
                unsigned long long x2 = pack2(xv[k], xv[k]);
#pragma unroll
                for (int m = 0; m < 9; ++m) fma2(acc[m], wp[m], x2);
            }
        }
        __syncthreads();
    }

    float* ob = g_off + ((size_t)b * 18) * HW_ + (h0 + rt) * W_ + wc;
#pragma unroll
    for (int m = 0; m < 9; ++m) {
        float2 v = unpack2(acc[m]);
        ob[(2 * m) * HW_]     = v.x + b_off[2 * m];
        ob[(2 * m + 1) * HW_] = v.y + b_off[2 * m + 1];
    }
}

// ===========================================================================
// Kernel 2a/2b: split w_def / w_sc into bf16 hi / lo planes
// ===========================================================================
__global__ __launch_bounds__(1024)
void k_wsplit(const float* __restrict__ w) {
    int i = blockIdx.x * 1024 + threadIdx.x;
    float v = w[i];
    __nv_bfloat16 h = __float2bfloat16(v);
    float vh = __bfloat162float(h);
    __nv_bfloat16 l = __float2bfloat16(v - vh);
    g_wh[i] = __bfloat16_as_ushort(h);
    g_wl[i] = __bfloat16_as_ushort(l);
}
__global__ __launch_bounds__(1024)
void k_wscsplit(const float* __restrict__ w) {
    int i = blockIdx.x * 1024 + threadIdx.x;
    float v = w[i];
    __nv_bfloat16 h = __float2bfloat16(v);
    float vh = __bfloat162float(h);
    __nv_bfloat16 l = __float2bfloat16(v - vh);
    g_wsh[i] = __bfloat16_as_ushort(h);
    g_wsl[i] = __bfloat16_as_ushort(l);
}

// ===========================================================================
// Kernel 2c: transpose+split x -> g_xh/g_xl [pixel][cin]
// ===========================================================================
__global__ __launch_bounds__(256, 2)
void k_xsplit(const float* __restrict__ x) {
    __shared__ float xs[CIN_ * 65];
    const int tid = threadIdx.x;
    const int blk = blockIdx.x;
    const int b   = blk >> 6;
    const int h   = blk & 63;

    const float* xb = x + ((size_t)b * CIN_) * HW_ + h * 64;
#pragma unroll 8
    for (int i = 0; i < 32; ++i) {
        int e = tid + i * 256;
        int c = e >> 6, p = e & 63;
        xs[c * 65 + p] = xb[(size_t)c * HW_ + p];
    }
    __syncthreads();

    ushort* oh = g_xh + (size_t)(b * HW_ + h * 64) * CIN_;
    ushort* ol = g_xl + (size_t)(b * HW_ + h * 64) * CIN_;
#pragma unroll 8
    for (int i = 0; i < 32; ++i) {
        int e = tid + i * 256;
        int p = e >> 7, c = e & 127;
        float v = xs[c * 65 + p];
        __nv_bfloat16 hh = __float2bfloat16(v);
        float vh = __bfloat162float(hh);
        __nv_bfloat16 ll = __float2bfloat16(v - vh);
        oh[p * CIN_ + c] = __bfloat16_as_ushort(hh);
        ol[p * CIN_ + c] = __bfloat16_as_ushort(ll);
    }
}

// ===========================================================================
// Kernel 3: im2col — deformable bilinear gather -> bf16 hi/lo planes,
// S layout [pixel][1152]. Packed u32 stores (2 adjacent k per store).
// ===========================================================================
#define ICH  32
#define IKC  (ICH * 9)

__global__ __launch_bounds__(256, 2)
void k_im2col(const float* __restrict__ x) {
    extern __shared__ float smI[];
    float*  samp  = smI;                               // [288][65]
    int4*   tap_a = (int4*)(smI + IKC * 65);           // 576
    float4* tap_w = (float4*)(tap_a + 64 * 9);         // 576

    const int tid  = threadIdx.x;
    const int wid  = tid >> 5;
    const int lid  = tid & 31;
    const int blk  = blockIdx.x;
    const int bimg = blk >> 6;
    const int h    = blk & 63;

    for (int idx = tid; idx < 64 * 9; idx += 256) {
        int p = idx / 9;
        int k = idx - p * 9;
        const float* offb = g_off + ((size_t)bimg * 18) * HW_ + h * W_ + p;
        float dy = offb[(size_t)(2 * k) * HW_];
        float dx = offb[(size_t)(2 * k + 1) * HW_];
        float py = (float)(h + (k / 3) - 1) + dy;
        float px = (float)(p + (k % 3) - 1) + dx;
        float y0 = floorf(py), x0 = floorf(px);
        float fy = py - y0,    fx = px - x0;
        int iy = (int)y0, ix = (int)x0;
        float w00 = (1.f - fy) * (1.f - fx);
        float w01 = (1.f - fy) * fx;
        float w10 = fy * (1.f - fx);
        float w11 = fy * fx;
        int4 ad; float4 wt;
        bool vy0 = (iy >= 0)     && (iy < H_);
        bool vy1 = (iy + 1 >= 0) && (iy + 1 < H_);
        bool vx0 = (ix >= 0)     && (ix < W_);
        bool vx1 = (ix + 1 >= 0) && (ix + 1 < W_);
        ad.x = (vy0 && vx0) ? (iy * W_ + ix)           : 0;  wt.x = (vy0 && vx0) ? w00 : 0.f;
        ad.y = (vy0 && vx1) ? (iy * W_ + ix + 1)       : 0;  wt.y = (vy0 && vx1) ? w01 : 0.f;
        ad.z = (vy1 && vx0) ? ((iy + 1) * W_ + ix)     : 0;  wt.z = (vy1 && vx0) ? w10 : 0.f;
        ad.w = (vy1 && vx1) ? ((iy + 1) * W_ + ix + 1) : 0;  wt.w = (vy1 && vx1) ? w11 : 0.f;
        tap_a[idx] = ad;
        tap_w[idx] = wt;
    }
    __syncthreads();

    const float* xb = x + ((size_t)bimg * CIN_) * HW_;
    const size_t rowbase = (size_t)(bimg * HW_ + h * W_) * KTOT;

    for (int c0 = 0; c0 < CIN_; c0 += ICH) {
#pragma unroll 4
        for (int i = 0; i < IKC * 64 / 256; ++i) {
            int e  = i * 256 + tid;
            int p  = e & 63;
            int kk = e >> 6;
            int c  = kk / 9;
            int k  = kk - c * 9;
            int ti = p * 9 + k;
            int4   ad = tap_a[ti];
            float4 wt = tap_w[ti];
            const float* xc = xb + (size_t)(c0 + c) * HW_;
            samp[kk * 65 + p] = wt.x * __ldg(xc + ad.x) + wt.y * __ldg(xc + ad.y)
                              + wt.z * __ldg(xc + ad.z) + wt.w * __ldg(xc + ad.w);
        }
        __syncthreads();

        // transposed writeout: warp owns 8 pixels; lane packs 2 adjacent k
        for (int pi = 0; pi < 8; ++pi) {
            int p = wid * 8 + pi;
            size_t rb = rowbase + (size_t)p * KTOT + c0 * 9;   // even
            unsigned* rh32 = (unsigned*)(g_sh + rb);
            unsigned* rl32 = (unsigned*)(g_sl + rb);
#pragma unroll
            for (int pass = 0; pass < 5; ++pass) {
                int u = pass * 32 + lid;           // u32 index, 144 total
                if (u < 144) {
                    float v0 = samp[(2 * u)     * 65 + p];
                    float v1 = samp[(2 * u + 1) * 65 + p];
                    __nv_bfloat16 h0 = __float2bfloat16(v0);
                    __nv_bfloat16 h1 = __float2bfloat16(v1);
                    float r0 = v0 - __bfloat162float(h0);
                    float r1 = v1 - __bfloat162float(h1);
                    __nv_bfloat16 l0 = __float2bfloat16(r0);
                    __nv_bfloat16 l1 = __float2bfloat16(r1);
                    rh32[u] = (unsigned)__bfloat16_as_ushort(h0)
                            | ((unsigned)__bfloat16_as_ushort(h1) << 16);
                    rl32[u] = (unsigned)__bfloat16_as_ushort(l0)
                            | ((unsigned)__bfloat16_as_ushort(l1) << 16);
                }
            }
        }
        __syncthreads();
    }
}

// ===========================================================================
// Kernel 4: HMMA GEMM.  Block = M128 x N64, grid (2, 512):
// blockIdx.x = mtile (fast-varying) so the two blocks sharing a B tile are
// adjacent in launch order -> second read hits L2 instead of DRAM.
// 8 warps: 4M x 2N, warp tile 32x32. ldmatrix frags, round-13 LDG->STS staging.
// Main: g_y = W_def * S + b_def (K=1152). Then shortcut: g_sc = W_sc * X + b_sc.
// smem rows: 64 ushorts = 128B = 8 x 16B sectors, sector ^= (row & 7).
// ===========================================================================
#define KC 64
#define OF_AH 0
#define OF_AL 16384
#define OF_BH 32768
#define OF_BL 40960
#define SMEMG 49152

__device__ __forceinline__ void stage_AB(
    char* bb, int tid,
    const ushort* __restrict__ Ah, const ushort* __restrict__ Al, int strideA,
    const ushort* __restrict__ Bh, const ushort* __restrict__ Bl, int strideB)
{
    // LDG phase: batched, coalesced (8 lanes cover one 128B row chunk)
    uint4 ra[8];
#pragma unroll
    for (int it = 0; it < 8; ++it) {
        int idx  = tid + it * 256;       // 0..2047 (2 planes x 128 rows x 8 sec)
        int plane = idx >> 10;
        int rem   = idx & 1023;
        int row   = rem >> 3;
        int s     = rem & 7;
        const ushort* base = plane ? Al : Ah;
        ra[it] = *(const uint4*)(base + (size_t)row * strideA + s * 8);
    }
    uint4 rb[4];
#pragma unroll
    for (int it = 0; it < 4; ++it) {
        int idx  = tid + it * 256;       // 0..1023 (2 planes x 64 rows x 8 sec)
        int plane = idx >> 9;
        int rem   = idx & 511;
        int row   = rem >> 3;
        int s     = rem & 7;
        const ushort* base = plane ? Bl : Bh;
        rb[it] = *(const uint4*)(base + (size_t)row * strideB + s * 8);
    }

    __syncthreads();   // previous chunk's compute done -> buffer reusable

    // STS phase: XOR-sector swizzle, conflict-free per quarter-warp
#pragma unroll
    for (int it = 0; it < 8; ++it) {
        int idx  = tid + it * 256;
        int plane = idx >> 10;
        int rem   = idx & 1023;
        int row   = rem >> 3;
        int s     = rem & 7;
        *(uint4*)(bb + (plane ? OF_AL : OF_AH) + row * 128
                  + ((s ^ (row & 7)) << 4)) = ra[it];
    }
#pragma unroll
    for (int it = 0; it < 4; ++it) {
        int idx  = tid + it * 256;
        int plane = idx >> 9;
        int rem   = idx & 511;
        int row   = rem >> 3;
        int s     = rem & 7;
        *(uint4*)(bb + (plane ? OF_BL : OF_BH) + row * 128
                  + ((s ^ (row & 7)) << 4)) = rb[it];
    }
}

struct FragCtx {
    uint32_t aoff[2]; int ar7[2]; int asec;
    uint32_t boff[2]; int br7[2]; int bsec;
};

__device__ __forceinline__ void gemm_chunk(float acc[2][4][4],
                                           uint32_t bb, const FragCtx& fc)
{
#pragma unroll
    for (int ks = 0; ks < 4; ++ks) {
        unsigned aH[2][4], aL[2][4], bH[4][2], bL[4][2];
#pragma unroll
        for (int mf = 0; mf < 2; ++mf) {
            uint32_t so = (uint32_t)((((ks * 2 + fc.asec) ^ fc.ar7[mf])) << 4);
            LDSM4(aH[mf][0], aH[mf][1], aH[mf][2], aH[mf][3],
                  bb + OF_AH + fc.aoff[mf] + so);
            LDSM4(aL[mf][0], aL[mf][1], aL[mf][2], aL[mf][3],
                  bb + OF_AL + fc.aoff[mf] + so);
        }
#pragma unroll
        for (int j = 0; j < 2; ++j) {
            uint32_t so = (uint32_t)((((ks * 2 + fc.bsec) ^ fc.br7[j])) << 4);
            LDSM4(bH[2 * j][0], bH[2 * j][1], bH[2 * j + 1][0], bH[2 * j + 1][1],
                  bb + OF_BH + fc.boff[j] + so);
            LDSM4(bL[2 * j][0], bL[2 * j][1], bL[2 * j + 1][0], bL[2 * j + 1][1],
                  bb + OF_BL + fc.boff[j] + so);
        }
#pragma unroll
        for (int mf = 0; mf < 2; ++mf)
#pragma unroll
            for (int nf = 0; nf < 4; ++nf) {
                hmma(acc[mf][nf], aH[mf], bH[nf]);
                hmma(acc[mf][nf], aH[mf], bL[nf]);
                hmma(acc[mf][nf], aL[mf], bH[nf]);
            }
    }
}

__device__ __forceinline__ void store_tile(
    float* __restrict__ gbase, const float acc[2][4][4],
    const float* __restrict__ bias_arr,
    int mtile, int wm, int wn, int lane, int bimg, int poff)
{
    const int rquad = lane >> 2;
    const int dcol  = (lane & 3) * 2;
#pragma unroll
    for (int mf = 0; mf < 2; ++mf)
#pragma unroll
        for (int hr = 0; hr < 2; ++hr) {
            int cout = mtile * 128 + wm * 32 + mf * 16 + hr * 8 + rquad;
            float bias = __ldg(bias_arr + cout);
            float* dst = gbase + ((size_t)(bimg * COUT_ + cout)) * HW_
                       + poff + wn * 32 + dcol;
#pragma unroll
            for (int nf = 0; nf < 4; ++nf) {
                float2 v;
                v.x = acc[mf][nf][hr * 2 + 0] + bias;
                v.y = acc[mf][nf][hr * 2 + 1] + bias;
                *(float2*)(dst + nf * 8) = v;
            }
        }
}

__global__ __launch_bounds__(256, 2)
void k_gemm(const float* __restrict__ b_def, const float* __restrict__ b_sc) {
    extern __shared__ char smG[];
    const uint32_t smb = smem_u32(smG);

    const int tid  = threadIdx.x;
    const int lane = tid & 31;
    const int wid  = tid >> 5;
    const int wm   = wid & 3;           // 4 M-warps x 32 rows
    const int wn   = wid >> 2;          // 2 N-warps x 32 cols

    const int mtile = blockIdx.x;       // fast-varying -> B-tile L2 reuse
    const int pix0  = blockIdx.y * 64;
    const int bimg  = pix0 >> 12;
    const int poff  = pix0 & 4095;

    FragCtx fc;
#pragma unroll
    for (int mf = 0; mf < 2; ++mf) {
        int row = wm * 32 + mf * 16 + ((lane >> 3) & 1) * 8 + (lane & 7);
        fc.aoff[mf] = row * 128;
        fc.ar7[mf]  = row & 7;
    }
    fc.asec = lane >> 4;
#pragma unroll
    for (int j = 0; j < 2; ++j) {
        int row = wn * 32 + j * 16 + ((lane >> 4) & 1) * 8 + (lane & 7);
        fc.boff[j] = row * 128;
        fc.br7[j]  = row & 7;
    }
    fc.bsec = (lane >> 3) & 1;

    float acc[2][4][4];
#pragma unroll
    for (int mf = 0; mf < 2; ++mf)
#pragma unroll
        for (int nf = 0; nf < 4; ++nf)
#pragma unroll
            for (int q = 0; q < 4; ++q) acc[mf][nf][q] = 0.f;

    // ---- main GEMM: K = 1152 ----
    const ushort* Ah = g_wh + (size_t)(mtile * 128) * KTOT;
    const ushort* Al = g_wl + (size_t)(mtile * 128) * KTOT;
    const ushort* Bh = g_sh + (size_t)pix0 * KTOT;
    const ushort* Bl = g_sl + (size_t)pix0 * KTOT;

    for (int ch = 0; ch < KTOT / KC; ++ch) {
        const int k0 = ch * KC;
        stage_AB(smG, tid, Ah + k0, Al + k0, KTOT, Bh + k0, Bl + k0, KTOT);
        __syncthreads();
        gemm_chunk(acc, smb, fc);
    }
    store_tile(g_y, acc, b_def, mtile, wm, wn, lane, bimg, poff);

    // ---- shortcut GEMM: K = 128 (2 chunks) ----
#pragma unroll
    for (int mf = 0; mf < 2; ++mf)
#pragma unroll
        for (int nf = 0; nf < 4; ++nf)
#pragma unroll
            for (int q = 0; q < 4; ++q) acc[mf][nf][q] = 0.f;

    const ushort* Ash = g_wsh + (size_t)(mtile * 128) * CIN_;
    const ushort* Asl = g_wsl + (size_t)(mtile * 128) * CIN_;
    const ushort* Bsh = g_xh + (size_t)pix0 * CIN_;
    const ushort* Bsl = g_xl + (size_t)pix0 * CIN_;

    for (int ch = 0; ch < 2; ++ch) {
        const int k0 = ch * KC;
        stage_AB(smG, tid, Ash + k0, Asl + k0, CIN_, Bsh + k0, Bsl + k0, CIN_);
        __syncthreads();
        gemm_chunk(acc, smb, fc);
    }
    store_tile(g_sc, acc, b_sc, mtile, wm, wn, lane, bimg, poff);
}

// ===========================================================================
// Kernel 5: BN batch stats
// ===========================================================================
__global__ __launch_bounds__(256)
void k_stats(const float* __restrict__ gamma, const float* __restrict__ beta) {
    const int co = blockIdx.x;
    const int t  = threadIdx.x;
    float s = 0.f, s2 = 0.f;
    for (int b = 0; b < B_; ++b) {
        const float* yb = g_y + ((size_t)(b * COUT_ + co)) * HW_;
        for (int i = t * 4; i < HW_; i += 1024) {
            float4 v = *(const float4*)(yb + i);
            s  += v.x + v.y + v.z + v.w;
            s2 += v.x * v.x + v.y * v.y + v.z * v.z + v.w * v.w;
        }
    }
    __shared__ float rs[256], rq[256];
    rs[t] = s; rq[t] = s2;
    __syncthreads();
    for (int off = 128; off; off >>= 1) {
        if (t < off) { rs[t] += rs[t + off]; rq[t] += rq[t + off]; }
        __syncthreads();
    }
    if (t == 0) {
        const float inv_n = 1.f / (float)(B_ * HW_);
        float mean = rs[0] * inv_n;
        float var  = rq[0] * inv_n - mean * mean;
        float istd = rsqrtf(var + EPS_);
        float g = gamma[co];
        g_scale[co] = g * istd;
        g_shift[co] = beta[co] - mean * g * istd;
    }
}

// ===========================================================================
// Kernel 6: elementwise  out = relu(y*scale + shift + sc)
// ===========================================================================
__global__ __launch_bounds__(256)
void k_final(float* __restrict__ out) {
    const size_t idx = ((size_t)blockIdx.x * 256 + threadIdx.x) * 4;
    const int c = (int)((idx >> 12) & 255);
    const float sc = g_scale[c];
    const float sh = g_shift[c];
    float4 y = *(const float4*)(g_y + idx);
    float4 s = *(const float4*)(g_sc + idx);
    float4 r;
    r.x = fmaxf(fmaf(y.x, sc, sh) + s.x, 0.f);
    r.y = fmaxf(fmaf(y.y, sc, sh) + s.y, 0.f);
    r.z = fmaxf(fmaf(y.z, sc, sh) + s.z, 0.f);
    r.w = fmaxf(fmaf(y.w, sc, sh) + s.w, 0.f);
    *(float4*)(out + idx) = r;
}

// ===========================================================================
extern "C" void kernel_launch(void* const* d_in, const int* in_sizes, int n_in,
                              void* d_out, int out_size) {
    const float* x     = (const float*)d_in[0];
    const float* w_off = (const float*)d_in[1];
    const float* b_off = (const float*)d_in[2];
    const float* w_def = (const float*)d_in[3];
    const float* b_def = (const float*)d_in[4];
    const float* gamma = (const float*)d_in[5];
    const float* beta  = (const float*)d_in[6];
    const float* w_sc  = (const float*)d_in[7];
    const float* b_sc  = (const float*)d_in[8];
    float* out = (float*)d_out;

    const int smem1 = (20736 + 8 * 396) * 4;
    const int smemI = (IKC * 65) * 4 + 64 * 9 * (sizeof(int4) + sizeof(float4));

    cudaFuncSetAttribute(k_offset, cudaFuncAttributeMaxDynamicSharedMemorySize, smem1);
    cudaFuncSetAttribute(k_im2col, cudaFuncAttributeMaxDynamicSharedMemorySize, smemI);
    cudaFuncSetAttribute(k_gemm,   cudaFuncAttributeMaxDynamicSharedMemorySize, SMEMG);

    k_offset<<<dim3(16, 8), 256, smem1>>>(x, w_off, b_off);
    k_wsplit<<<288, 1024>>>(w_def);
    k_wscsplit<<<32, 1024>>>(w_sc);
    k_xsplit<<<512, 256>>>(x);
    k_im2col<<<512, 256, smemI>>>(x);
    k_gemm<<<dim3(2, 512), 256, SMEMG>>>(b_def, b_sc);
    k_stats<<<256, 256>>>(gamma, beta);
    k_final<<<8192, 256>>>(out);
}